// round 17
// baseline (speedup 1.0000x reference)
#include <cuda_runtime.h>

// [Resubmission — R14/R16 infra failures; PDL variant has never executed.]
//
// B=8, MSP=2048, D=512, A=64, NB=5
// Exact contraction reordering:
//   Wc[n,d]   = W_fl[n,d] + W_fl[n,512+d]
//   S[n]      = sum_d Wc[n,d]
//   t[b,s,n]  = sum_d e[b,s,d] * Wc[n,d]
//   out[b,a,n]= sum_s W_ll[a,s] * t[b,s,n] + b_ll[a]*S[n] + b_fl[n]
//   final[b,i,j,n] = out[b,i,n]
//
// R15 kernels unchanged + PDL: out_kernel launched with programmatic
// stream serialization; its W_ll loads run BEFORE
// cudaGridDependencySynchronize(), overlapping t_kernel's tail.
// Falls back to a plain launch if the attribute is rejected.

#define NROWS  16384      // B * MSP
#define DVAL   512
#define NB     5
#define AVAL   64
#define BVAL   8
#define MSP    2048
#define NWARPT (296 * 6)  // t_kernel warps

__device__ float g_S[NB];
__device__ float g_t[NROWS * NB];          // 320 KB scratch

// Packed f32x2 FMA (Blackwell)
__device__ __forceinline__ unsigned long long fma2(unsigned long long a,
                                                   unsigned long long b,
                                                   unsigned long long c) {
    unsigned long long d;
    asm("fma.rn.f32x2 %0, %1, %2, %3;" : "=l"(d) : "l"(a), "l"(b), "l"(c));
    return d;
}
__device__ __forceinline__ float unpack_add(unsigned long long v) {
    float lo, hi;
    asm("mov.b64 {%0, %1}, %2;" : "=f"(lo), "=f"(hi) : "l"(v));
    return lo + hi;
}

__device__ __forceinline__ void load_row(ulonglong2 (&ev)[4],
                                         const float* __restrict__ e,
                                         int row, int lane) {
    const ulonglong2* er = (const ulonglong2*)(e + (size_t)row * DVAL);
    ev[0] = er[lane];
    ev[1] = er[32 + lane];
    ev[2] = er[64 + lane];
    ev[3] = er[96 + lane];
}

__device__ __forceinline__ void dot_row(float (&t)[NB],
                                        const ulonglong2 (&ev)[4],
                                        const ulonglong2 (&wc2)[4][NB]) {
    unsigned long long acc2[NB];
    #pragma unroll
    for (int n = 0; n < NB; n++) acc2[n] = 0ull;
    #pragma unroll
    for (int r = 0; r < 4; r++) {
        #pragma unroll
        for (int n = 0; n < NB; n++) {
            acc2[n] = fma2(ev[r].x, wc2[r][n].x, acc2[n]);
            acc2[n] = fma2(ev[r].y, wc2[r][n].y, acc2[n]);
        }
    }
    #pragma unroll
    for (int n = 0; n < NB; n++) t[n] = unpack_add(acc2[n]);
}

__device__ __forceinline__ void reduce_store(float (&t)[NB], int row, int lane) {
    #pragma unroll
    for (int n = 0; n < NB; n++) {
        #pragma unroll
        for (int off = 16; off > 0; off >>= 1)
            t[n] += __shfl_xor_sync(0xFFFFFFFFu, t[n], off);
    }
    if (lane == 0) {
        float* tp = &g_t[row * NB];
        #pragma unroll
        for (int n = 0; n < NB; n++) tp[n] = t[n];
    }
}

// ---------------------------------------------------------------------------
// Kernel 1: t. 296 blocks x 192 threads (2 blocks/SM). Two row streams/warp.
// ---------------------------------------------------------------------------
__global__ __launch_bounds__(192, 2) void t_kernel(const float* __restrict__ e,
                                                   const float* __restrict__ W_fl) {
    __shared__ __align__(16) float wcs[NB * DVAL];   // 10 KB
    const int tid  = threadIdx.x;
    const int lane = tid & 31;
    const int warp = tid >> 5;

    for (int i = tid; i < NB * DVAL; i += 192) {
        int n = i / DVAL, d = i - n * DVAL;
        wcs[i] = W_fl[n * 1024 + d] + W_fl[n * 1024 + 512 + d];
    }
    __syncthreads();

    if (blockIdx.x == 0 && warp == 0) {
        #pragma unroll
        for (int n = 0; n < NB; n++) {
            float s = 0.f;
            for (int d = lane; d < DVAL; d += 32) s += wcs[n * DVAL + d];
            #pragma unroll
            for (int off = 16; off > 0; off >>= 1)
                s += __shfl_xor_sync(0xFFFFFFFFu, s, off);
            if (lane == 0) g_S[n] = s;
        }
    }

    ulonglong2 wc2[4][NB];
    #pragma unroll
    for (int r = 0; r < 4; r++)
        #pragma unroll
        for (int n = 0; n < NB; n++)
            wc2[r][n] = *(const ulonglong2*)&wcs[n * DVAL + r * 128 + lane * 4];

    const int gw = blockIdx.x * 6 + warp;

    int rowA = gw;
    int rowB = gw + NWARPT;
    ulonglong2 evA[4], evB[4];
    if (rowA < NROWS) load_row(evA, e, rowA, lane);
    if (rowB < NROWS) load_row(evB, e, rowB, lane);

    while (rowA < NROWS) {
        {
            float t[NB];
            dot_row(t, evA, wc2);
            const int nA = rowA + 2 * NWARPT;
            if (nA < NROWS) load_row(evA, e, nA, lane);
            reduce_store(t, rowA, lane);
            rowA = nA;
        }
        if (rowB < NROWS) {
            float t[NB];
            dot_row(t, evB, wc2);
            const int nB = rowB + 2 * NWARPT;
            if (nB < NROWS) load_row(evB, e, nB, lane);
            reduce_store(t, rowB, lane);
            rowB = nB;
        }
    }
}

// ---------------------------------------------------------------------------
// Kernel 2: out + broadcast (R5 body) with PDL gate.
// grid = (64 a, 8 b) = 512 blocks, 256 threads.
// ---------------------------------------------------------------------------
__global__ __launch_bounds__(256) void out_kernel(const float* __restrict__ W_ll,
                                                  const float* __restrict__ b_ll,
                                                  const float* __restrict__ b_fl,
                                                  float* __restrict__ out) {
    __shared__ float partial[8 * NB];
    __shared__ float v[NB];
    const int a    = blockIdx.x;
    const int b    = blockIdx.y;
    const int tid  = threadIdx.x;
    const int lane = tid & 31;
    const int w    = tid >> 5;

    // ---- independent of t: overlaps t_kernel's tail under PDL ----
    const float* wrow = W_ll + (size_t)a * MSP + w * 256;
    float wv[8];
    #pragma unroll
    for (int k = 0; k < 8; k++) wv[k] = wrow[lane + 32 * k];
    const float blv = b_ll[a];

    // ---- wait for t_kernel results (no-op when launched plainly) ----
    cudaGridDependencySynchronize();

    const float* tbase = g_t + ((size_t)b * MSP + w * 256) * NB;
    float a0 = 0.f, a1 = 0.f, a2 = 0.f, a3 = 0.f, a4 = 0.f;
    #pragma unroll
    for (int k = 0; k < 8; k++) {
        const float* tp = &tbase[(lane + 32 * k) * NB];
        a0 += wv[k] * tp[0];
        a1 += wv[k] * tp[1];
        a2 += wv[k] * tp[2];
        a3 += wv[k] * tp[3];
        a4 += wv[k] * tp[4];
    }
    #pragma unroll
    for (int off = 16; off > 0; off >>= 1) {
        a0 += __shfl_xor_sync(0xFFFFFFFFu, a0, off);
        a1 += __shfl_xor_sync(0xFFFFFFFFu, a1, off);
        a2 += __shfl_xor_sync(0xFFFFFFFFu, a2, off);
        a3 += __shfl_xor_sync(0xFFFFFFFFu, a3, off);
        a4 += __shfl_xor_sync(0xFFFFFFFFu, a4, off);
    }
    if (lane == 0) {
        float* pp = &partial[w * NB];
        pp[0] = a0; pp[1] = a1; pp[2] = a2; pp[3] = a3; pp[4] = a4;
    }
    __syncthreads();

    if (tid < NB) {
        float s = 0.f;
        #pragma unroll
        for (int q = 0; q < 8; q++) s += partial[q * NB + tid];
        v[tid] = s + blv * g_S[tid] + b_fl[tid];
    }
    __syncthreads();

    float* base = out + ((size_t)(b * AVAL + a)) * (AVAL * NB);
    #pragma unroll
    for (int k = 0; k < 2; k++) {
        int idx = tid + k * 256;
        if (idx < AVAL * NB) base[idx] = v[idx % NB];
    }
}

// ---------------------------------------------------------------------------
extern "C" void kernel_launch(void* const* d_in, const int* in_sizes, int n_in,
                              void* d_out, int out_size) {
    const float* e    = (const float*)d_in[0];
    const float* W_ll = (const float*)d_in[1];
    const float* b_ll = (const float*)d_in[2];
    const float* W_fl = (const float*)d_in[3];
    const float* b_fl = (const float*)d_in[4];
    float* out = (float*)d_out;

    t_kernel<<<296, 192>>>(e, W_fl);

    // PDL launch; fall back to a plain launch if the attribute is rejected.
    cudaLaunchConfig_t cfg = {};
    cfg.gridDim  = dim3(AVAL, BVAL, 1);
    cfg.blockDim = dim3(256, 1, 1);
    cfg.dynamicSmemBytes = 0;
    cfg.stream = 0;   // same (capture) stream as t_kernel
    cudaLaunchAttribute attr[1];
    attr[0].id = cudaLaunchAttributeProgrammaticStreamSerialization;
    attr[0].val.programmaticStreamSerializationAllowed = 1;
    cfg.attrs = attr;
    cfg.numAttrs = 1;
    cudaError_t err = cudaLaunchKernelEx(&cfg, out_kernel, W_ll, b_ll, b_fl, out);
    if (err != cudaSuccess) {
        (void)cudaGetLastError();   // clear sticky error, then plain launch
        out_kernel<<<dim3(AVAL, BVAL), 256>>>(W_ll, b_ll, b_fl, out);
    }
}